// round 10
// baseline (speedup 1.0000x reference)
#include <cuda_runtime.h>
#include <cuda_fp16.h>
#include <cstdint>

#define B_    64
#define N_    2048
#define JD_   512
#define EPS_  1e-8f
#define SROW  136   // smem row stride in halves (272 B): conflict-free frag stores

// Scratch (device globals: allocation-free rule)
__device__ __half g_u[(size_t)B_ * N_ * JD_];        // 134 MB u[b][i][jd] fp16
__device__ float  g_part1[(size_t)128 * B_ * JD_];   // s1 partials (128 chunks)
__device__ float  g_part2[(size_t)16 * B_ * JD_];    // 16-chunk partials (s1/s2/s3)
__device__ float  g_v[2][B_ * JD_];                  // v1, (v1+v2)

__device__ __forceinline__ uint32_t packh2(float a, float b) {
    __half2 h = __floats2half2_rn(a, b);
    return *(uint32_t*)&h;
}
__device__ __forceinline__ void mma16816(float& d0, float& d1, float& d2, float& d3,
        uint32_t a0, uint32_t a1, uint32_t a2, uint32_t a3,
        uint32_t b0, uint32_t b1) {
    asm volatile(
        "mma.sync.aligned.m16n8k16.row.col.f32.f16.f16.f32 "
        "{%0,%1,%2,%3}, {%4,%5,%6,%7}, {%8,%9}, {%10,%11,%12,%13};\n"
        : "=f"(d0), "=f"(d1), "=f"(d2), "=f"(d3)
        : "r"(a0), "r"(a1), "r"(a2), "r"(a3), "r"(b0), "r"(b1),
          "f"(0.f), "f"(0.f), "f"(0.f), "f"(0.f));
}

// ---------------------------------------------------------------------------
// k_u (round-5/7/9 proven config): tensor-core einsum -> u (fp16, coalesced
// via smem transpose) + fused pass-1 partials (uniform c = 1/32, fp32 acc).
// Grid 128 (16 i each), 512 thr = 16 warps; warp = (mt: 16 b) x (jdr: 128 jd).
// ---------------------------------------------------------------------------
__global__ __launch_bounds__(512, 1) void k_u(const float* __restrict__ x,
                                              const float* __restrict__ w) {
    extern __shared__ __half us[];       // 16 warps * 16 rows * SROW halves
    const int ic   = blockIdx.x;
    const int t    = threadIdx.x;
    const int wid  = t >> 5;
    const int lane = t & 31;
    const int g    = lane >> 2;
    const int tg   = lane & 3;
    const int mt   = wid & 3;
    const int jdr  = wid >> 2;
    const int jd0  = jdr * 128;
    const int row0 = mt * 16 + g;
    const int row1 = row0 + 8;
    __half* usw = us + wid * 16 * SROW;  // this warp's 16x128 tile

    float acc[16][4];
#pragma unroll
    for (int q = 0; q < 16; q++)
#pragma unroll
        for (int r = 0; r < 4; r++) acc[q][r] = 0.f;

    for (int k = 0; k < 16; k++) {
        const int i = ic * 16 + k;

        // A fragment from fp32 x
        const float* xp0 = x + ((size_t)row0 * N_ + i) * 16 + 2 * tg;
        const float* xp1 = x + ((size_t)row1 * N_ + i) * 16 + 2 * tg;
        float2 f0 = *(const float2*)xp0;
        float2 f1 = *(const float2*)xp1;
        float2 f2 = *(const float2*)(xp0 + 8);
        float2 f3 = *(const float2*)(xp1 + 8);
        uint32_t A0 = packh2(f0.x, f0.y);
        uint32_t A1 = packh2(f1.x, f1.y);
        uint32_t A2 = packh2(f2.x, f2.y);
        uint32_t A3 = packh2(f3.x, f3.y);

#pragma unroll
        for (int q = 0; q < 16; q++) {
            const int col = jd0 + q * 8 + g;
            const float* wp = w + ((size_t)i * JD_ + col) * 16 + 2 * tg;
            float2 w0 = *(const float2*)wp;
            float2 w1 = *(const float2*)(wp + 8);
            uint32_t Bb0 = packh2(w0.x, w0.y);
            uint32_t Bb1 = packh2(w1.x, w1.y);

            float d0, d1, d2, d3;
            mma16816(d0, d1, d2, d3, A0, A1, A2, A3, Bb0, Bb1);
            acc[q][0] += d0; acc[q][1] += d1;
            acc[q][2] += d2; acc[q][3] += d3;

            // stage fragments: row-local col q*8+2tg, rows g / g+8
            *(uint32_t*)(usw + g * SROW       + q * 8 + 2 * tg) = packh2(d0, d1);
            *(uint32_t*)(usw + (g + 8) * SROW + q * 8 + 2 * tg) = packh2(d2, d3);
        }
        __syncwarp();

        // coalesced copy-out: 16 rows x 256 B -> u[b][i][jd0..jd0+128)
#pragma unroll
        for (int it = 0; it < 8; it++) {
            const int r   = it * 2 + (lane >> 4);
            const int off = lane & 15;
            uint4 v = *(const uint4*)(usw + r * SROW + off * 8);
            *(uint4*)(g_u + ((size_t)(mt * 16 + r) * N_ + i) * JD_ + jd0 + off * 8) = v;
        }
        __syncwarp();
    }

    // s1 partials: g_part1[ic][b][jd], scaled by 1/32
    float* pb = g_part1 + ((size_t)ic * B_ + row0) * JD_;
    const float cinv = 1.0f / 32.0f;
#pragma unroll
    for (int q = 0; q < 16; q++) {
        const int col = jd0 + q * 8 + 2 * tg;
        *(float2*)(pb + col)           = make_float2(acc[q][0] * cinv, acc[q][1] * cinv);
        *(float2*)(pb + 8 * JD_ + col) = make_float2(acc[q][2] * cinv, acc[q][3] * cinv);
    }
}

// ---------------------------------------------------------------------------
// Stage A of s1 reduce: 128 chunks -> 16 (high parallelism, 524288 threads).
// ---------------------------------------------------------------------------
__global__ void k_red1() {
    const int gidx = blockIdx.x * 256 + threadIdx.x;   // 2048 CTAs * 256
    const int grp  = gidx >> 15;                       // 0..15 (B_*JD_ = 32768)
    const int idx  = gidx & 32767;
    const float* p = g_part1 + (size_t)grp * 8 * (B_ * JD_) + idx;
    float s = 0.f;
#pragma unroll
    for (int c = 0; c < 8; c++)
        s += p[(size_t)c * B_ * JD_];
    g_part2[(size_t)grp * (B_ * JD_) + idx] = s;
}

// ---------------------------------------------------------------------------
// Routing sweep over fp16 u: TWO i's interleaved per iteration (two
// independent logit + shuffle-sum chains overlap; 4 LDG.128 in flight).
// No max-subtraction (logits bounded; softmax shift-invariant), fast division.
// Grid (16, 64), 256 thr = 8 warps, warp handles 16 i, lane = j.
// ---------------------------------------------------------------------------
__global__ __launch_bounds__(256, 3) void k_pass(int vIdx) {
    const int b    = blockIdx.y;
    const int ic   = blockIdx.x;
    const int t    = threadIdx.x;
    const int warp = t >> 5;
    const int j    = t & 31;

    __shared__ float vs[JD_];
    __shared__ float ss[8][JD_];

    for (int idx = t; idx < JD_; idx += 256)
        vs[idx] = g_v[vIdx][b * JD_ + idx];
    __syncthreads();

    __half2 vj2[8];
#pragma unroll
    for (int q = 0; q < 8; q++)
        vj2[q] = __floats2half2_rn(vs[j * 16 + 2 * q], vs[j * 16 + 2 * q + 1]);

    float acc[16];
#pragma unroll
    for (int d = 0; d < 16; d++) acc[d] = 0.f;

    const int ibase = ic * 128 + warp * 16;
    const uint4* ub = (const uint4*)(g_u + ((size_t)b * N_ + ibase) * JD_) + j * 2;

    // current pair (i = 0, 1)
    uint4 p0 = __ldcs(ub);
    uint4 p1 = __ldcs(ub + 1);
    uint4 p2 = __ldcs(ub + 64);
    uint4 p3 = __ldcs(ub + 65);

    for (int k = 0; k < 16; k += 2) {
        // prefetch next pair (clamped to the last pair; redundant loads OK)
        const int kn = (k < 14) ? k + 2 : 14;
        uint4 n0 = __ldcs(ub + (size_t)kn * 64);
        uint4 n1 = __ldcs(ub + (size_t)kn * 64 + 1);
        uint4 n2 = __ldcs(ub + (size_t)(kn + 1) * 64);
        uint4 n3 = __ldcs(ub + (size_t)(kn + 1) * 64 + 1);

        const __half2* ua = (const __half2*)&p0;   // i0 lo
        const __half2* ubq = (const __half2*)&p1;  // i0 hi
        const __half2* uc = (const __half2*)&p2;   // i1 lo
        const __half2* ud = (const __half2*)&p3;   // i1 hi

        // two independent logit chains
        __half2 h0 = __hmul2(ua[0], vj2[0]);
        __half2 h1 = __hmul2(uc[0], vj2[0]);
#pragma unroll
        for (int q = 1; q < 4; q++) {
            h0 = __hfma2(ua[q], vj2[q], h0);
            h1 = __hfma2(uc[q], vj2[q], h1);
        }
#pragma unroll
        for (int q = 0; q < 4; q++) {
            h0 = __hfma2(ubq[q], vj2[4 + q], h0);
            h1 = __hfma2(ud[q],  vj2[4 + q], h1);
        }
        float bl0 = __low2float(h0) + __high2float(h0);
        float bl1 = __low2float(h1) + __high2float(h1);

        // two interleaved softmax-sum chains over 32 j-lanes
        float e0 = __expf(bl0), e1 = __expf(bl1);
        float s0 = e0, s1 = e1;
#pragma unroll
        for (int o = 16; o > 0; o >>= 1) {
            s0 += __shfl_xor_sync(0xffffffffu, s0, o);
            s1 += __shfl_xor_sync(0xffffffffu, s1, o);
        }
        const float c0 = __fdividef(e0, s0);
        const float c1 = __fdividef(e1, s1);

        // acc += c0*u(i0) + c1*u(i1)
#pragma unroll
        for (int q = 0; q < 4; q++) {
            float2 a = __half22float2(ua[q]);
            float2 bq = __half22float2(ubq[q]);
            float2 c = __half22float2(uc[q]);
            float2 d = __half22float2(ud[q]);
            acc[2*q]     += c0 * a.x + c1 * c.x;
            acc[2*q+1]   += c0 * a.y + c1 * c.y;
            acc[8+2*q]   += c0 * bq.x + c1 * d.x;
            acc[8+2*q+1] += c0 * bq.y + c1 * d.y;
        }

        p0 = n0; p1 = n1; p2 = n2; p3 = n3;
    }

#pragma unroll
    for (int d = 0; d < 16; d++) ss[warp][d * 32 + j] = acc[d];
    __syncthreads();

    for (int idx = t; idx < JD_; idx += 256) {
        int d = idx >> 5, jj = idx & 31;
        float r = 0.f;
#pragma unroll
        for (int wi = 0; wi < 8; wi++) r += ss[wi][idx];
        g_part2[((size_t)ic * B_ + b) * JD_ + jj * 16 + d] = r;
    }
}

// ---------------------------------------------------------------------------
// Reduce g_part2 over 16 chunks, then squash.
// mode 0: g_v[0] = squash_J(s)             (v1)
// mode 1: g_v[1] = squash_J(s) + g_v[0]    (v1 + v2, additive logits)
// mode 2: out    = squash_D(s)
// ---------------------------------------------------------------------------
__global__ void k_squash(int mode, float* __restrict__ out) {
    const int b = blockIdx.x;
    const int t = threadIdx.x;     // t = j*16 + d
    const float* p = g_part2 + (size_t)b * JD_ + t;
    float s = 0.f;
#pragma unroll
    for (int ic = 0; ic < 16; ic++)
        s += p[(size_t)ic * B_ * JD_];

    if (mode == 2) {
        float q = s * s;
#pragma unroll
        for (int o = 1; o < 16; o <<= 1)   // 16 consecutive lanes = same j
            q += __shfl_xor_sync(0xffffffffu, q, o);
        out[b * JD_ + t] = s * (q / (1.f + q)) * rsqrtf(q + EPS_);
        return;
    }

    __shared__ float sq[16];
    if (t < 16) sq[t] = 0.f;
    __syncthreads();
    atomicAdd(&sq[t & 15], s * s);
    __syncthreads();
    float q = sq[t & 15];
    float v = s * (q / (1.f + q)) * rsqrtf(q + EPS_);
    if (mode == 0) g_v[0][b * JD_ + t] = v;
    else           g_v[1][b * JD_ + t] = v + g_v[0][b * JD_ + t];
}

// ---------------------------------------------------------------------------
extern "C" void kernel_launch(void* const* d_in, const int* in_sizes, int n_in,
                              void* d_out, int out_size) {
    const float* x = (const float*)d_in[0];
    const float* w = (const float*)d_in[1];
    if (in_sizes[0] != B_ * N_ * 16) {       // defensive input-order check
        x = (const float*)d_in[1];
        w = (const float*)d_in[0];
    }

    const int smemB = 16 * 16 * SROW * 2;    // 69632 B
    cudaFuncSetAttribute(k_u, cudaFuncAttributeMaxDynamicSharedMemorySize, smemB);

    k_u<<<128, 512, smemB>>>(x, w);              // u fp16 + s1 partials (128 chunks)
    k_red1<<<2048, 256>>>();                     // s1: 128 -> 16 chunks
    k_squash<<<B_, JD_>>>(0, nullptr);           // v1 = squash_J(s1)
    dim3 pg(16, B_);
    k_pass<<<pg, 256>>>(0);                      // iter 2: softmax(u.v1) -> s2
    k_squash<<<B_, JD_>>>(1, nullptr);           // vsum = squash_J(s2) + v1
    k_pass<<<pg, 256>>>(1);                      // final: softmax(u.vsum) -> s3
    k_squash<<<B_, JD_>>>(2, (float*)d_out);     // out = squash_D(s3)
}

// round 11
// speedup vs baseline: 1.1183x; 1.1183x over previous
#include <cuda_runtime.h>
#include <cuda_fp16.h>
#include <cstdint>

#define B_    64
#define N_    2048
#define JD_   512
#define EPS_  1e-8f
#define SROW  136   // smem row stride in halves (272 B): conflict-free frag stores
#define NCH   148   // k_u i-chunks: 124 CTAs x 14 i + 24 CTAs x 13 i = 2048

// Scratch (device globals: allocation-free rule)
__device__ __half g_u[(size_t)B_ * N_ * JD_];        // 134 MB u[b][i][jd] fp16
__device__ float  g_part1[(size_t)NCH * B_ * JD_];   // s1 partials (148 chunks)
__device__ float  g_part2[(size_t)16 * B_ * JD_];    // 16-chunk partials (s1/s2/s3)
__device__ float  g_v[2][B_ * JD_];                  // v1, (v1+v2)

__device__ __forceinline__ uint32_t packh2(float a, float b) {
    __half2 h = __floats2half2_rn(a, b);
    return *(uint32_t*)&h;
}
__device__ __forceinline__ void mma16816(float& d0, float& d1, float& d2, float& d3,
        uint32_t a0, uint32_t a1, uint32_t a2, uint32_t a3,
        uint32_t b0, uint32_t b1) {
    asm volatile(
        "mma.sync.aligned.m16n8k16.row.col.f32.f16.f16.f32 "
        "{%0,%1,%2,%3}, {%4,%5,%6,%7}, {%8,%9}, {%10,%11,%12,%13};\n"
        : "=f"(d0), "=f"(d1), "=f"(d2), "=f"(d3)
        : "r"(a0), "r"(a1), "r"(a2), "r"(a3), "r"(b0), "r"(b1),
          "f"(0.f), "f"(0.f), "f"(0.f), "f"(0.f));
}

// ---------------------------------------------------------------------------
// k_u: tensor-core einsum -> u (fp16, coalesced via smem transpose) + fused
// pass-1 partials (uniform c = 1/32, fp32 acc).
// Grid 148 (one CTA per SM; 14 or 13 i each), 512 thr = 16 warps;
// warp = (mt: 16 b) x (jdr: 128 jd). Inner structure proven in rounds 5-9.
// ---------------------------------------------------------------------------
__global__ __launch_bounds__(512, 1) void k_u(const float* __restrict__ x,
                                              const float* __restrict__ w) {
    extern __shared__ __half us[];       // 16 warps * 16 rows * SROW halves
    const int cta  = blockIdx.x;
    const int nI   = (cta < 124) ? 14 : 13;
    const int ib   = (cta < 124) ? cta * 14 : 1736 + (cta - 124) * 13;
    const int t    = threadIdx.x;
    const int wid  = t >> 5;
    const int lane = t & 31;
    const int g    = lane >> 2;
    const int tg   = lane & 3;
    const int mt   = wid & 3;
    const int jdr  = wid >> 2;
    const int jd0  = jdr * 128;
    const int row0 = mt * 16 + g;
    const int row1 = row0 + 8;
    __half* usw = us + wid * 16 * SROW;  // this warp's 16x128 tile

    float acc[16][4];
#pragma unroll
    for (int q = 0; q < 16; q++)
#pragma unroll
        for (int r = 0; r < 4; r++) acc[q][r] = 0.f;

    for (int k = 0; k < nI; k++) {
        const int i = ib + k;

        // A fragment from fp32 x
        const float* xp0 = x + ((size_t)row0 * N_ + i) * 16 + 2 * tg;
        const float* xp1 = x + ((size_t)row1 * N_ + i) * 16 + 2 * tg;
        float2 f0 = *(const float2*)xp0;
        float2 f1 = *(const float2*)xp1;
        float2 f2 = *(const float2*)(xp0 + 8);
        float2 f3 = *(const float2*)(xp1 + 8);
        uint32_t A0 = packh2(f0.x, f0.y);
        uint32_t A1 = packh2(f1.x, f1.y);
        uint32_t A2 = packh2(f2.x, f2.y);
        uint32_t A3 = packh2(f3.x, f3.y);

#pragma unroll
        for (int q = 0; q < 16; q++) {
            const int col = jd0 + q * 8 + g;
            const float* wp = w + ((size_t)i * JD_ + col) * 16 + 2 * tg;
            float2 w0 = *(const float2*)wp;
            float2 w1 = *(const float2*)(wp + 8);
            uint32_t Bb0 = packh2(w0.x, w0.y);
            uint32_t Bb1 = packh2(w1.x, w1.y);

            float d0, d1, d2, d3;
            mma16816(d0, d1, d2, d3, A0, A1, A2, A3, Bb0, Bb1);
            acc[q][0] += d0; acc[q][1] += d1;
            acc[q][2] += d2; acc[q][3] += d3;

            // stage fragments: row-local col q*8+2tg, rows g / g+8
            *(uint32_t*)(usw + g * SROW       + q * 8 + 2 * tg) = packh2(d0, d1);
            *(uint32_t*)(usw + (g + 8) * SROW + q * 8 + 2 * tg) = packh2(d2, d3);
        }
        __syncwarp();

        // coalesced copy-out: 16 rows x 256 B -> u[b][i][jd0..jd0+128) (streamed)
#pragma unroll
        for (int it = 0; it < 8; it++) {
            const int r   = it * 2 + (lane >> 4);
            const int off = lane & 15;
            uint4 v = *(const uint4*)(usw + r * SROW + off * 8);
            __stcs((uint4*)(g_u + ((size_t)(mt * 16 + r) * N_ + i) * JD_
                            + jd0 + off * 8), v);
        }
        __syncwarp();
    }

    // s1 partials: g_part1[cta][b][jd], scaled by 1/32
    float* pb = g_part1 + ((size_t)cta * B_ + row0) * JD_;
    const float cinv = 1.0f / 32.0f;
#pragma unroll
    for (int q = 0; q < 16; q++) {
        const int col = jd0 + q * 8 + 2 * tg;
        *(float2*)(pb + col)           = make_float2(acc[q][0] * cinv, acc[q][1] * cinv);
        *(float2*)(pb + 8 * JD_ + col) = make_float2(acc[q][2] * cinv, acc[q][3] * cinv);
    }
}

// ---------------------------------------------------------------------------
// Stage A of s1 reduce: 148 chunks -> 16 groups (12 groups of 9 + 4 of 10).
// 2048 CTAs x 256 thr = 524288 threads, one output element each.
// ---------------------------------------------------------------------------
__global__ void k_red1() {
    const int gidx = blockIdx.x * 256 + threadIdx.x;
    const int grp  = gidx >> 15;                       // 0..15 (B_*JD_ = 32768)
    const int idx  = gidx & 32767;
    const int cnt  = (grp < 12) ? 9 : 10;
    const int base = (grp < 12) ? grp * 9 : 108 + (grp - 12) * 10;
    const float* p = g_part1 + (size_t)base * (B_ * JD_) + idx;
    float s = 0.f;
#pragma unroll 10
    for (int c = 0; c < cnt; c++)
        s += p[(size_t)c * B_ * JD_];
    g_part2[(size_t)grp * (B_ * JD_) + idx] = s;
}

// ---------------------------------------------------------------------------
// Routing sweep over fp16 u, depth-1 prefetch, no max-subtraction softmax
// (round-9 proven: 64 regs, occ 45%, 28.3us).
// Grid (16, 64), 256 thr = 8 warps, warp handles 16 i, lane = j.
// ---------------------------------------------------------------------------
__global__ __launch_bounds__(256, 4) void k_pass(int vIdx) {
    const int b    = blockIdx.y;
    const int ic   = blockIdx.x;
    const int t    = threadIdx.x;
    const int warp = t >> 5;
    const int j    = t & 31;

    __shared__ float vs[JD_];
    __shared__ float ss[8][JD_];

    for (int idx = t; idx < JD_; idx += 256)
        vs[idx] = g_v[vIdx][b * JD_ + idx];
    __syncthreads();

    __half2 vj2[8];
#pragma unroll
    for (int q = 0; q < 8; q++)
        vj2[q] = __floats2half2_rn(vs[j * 16 + 2 * q], vs[j * 16 + 2 * q + 1]);

    float acc[16];
#pragma unroll
    for (int d = 0; d < 16; d++) acc[d] = 0.f;

    const int ibase = ic * 128 + warp * 16;
    const uint4* ub = (const uint4*)(g_u + ((size_t)b * N_ + ibase) * JD_) + j * 2;

    uint4 p0 = __ldcs(ub);
    uint4 p1 = __ldcs(ub + 1);
    for (int k = 0; k < 16; k++) {
        // prefetch next i (clamped; MLP overlap with softmax latency)
        const int kn = (k < 15) ? k + 1 : 15;
        uint4 n0 = __ldcs(ub + (size_t)kn * 64);
        uint4 n1 = __ldcs(ub + (size_t)kn * 64 + 1);

        // logit in half2
        const __half2* u2a = (const __half2*)&p0;
        const __half2* u2b = (const __half2*)&p1;
        __half2 h = __hmul2(u2a[0], vj2[0]);
#pragma unroll
        for (int q = 1; q < 4; q++) h = __hfma2(u2a[q], vj2[q], h);
#pragma unroll
        for (int q = 0; q < 4; q++) h = __hfma2(u2b[q], vj2[4 + q], h);
        float bl = __low2float(h) + __high2float(h);

        // softmax over 32 j-lanes, no max-subtraction (bounded logits)
        float ex = __expf(bl);
        float sum = ex;
#pragma unroll
        for (int o = 16; o > 0; o >>= 1)
            sum += __shfl_xor_sync(0xffffffffu, sum, o);
        const float c = __fdividef(ex, sum);

        // acc += c * u (fp32 unpack)
#pragma unroll
        for (int q = 0; q < 4; q++) {
            float2 ua = __half22float2(u2a[q]);
            float2 uc = __half22float2(u2b[q]);
            acc[2*q]     += c * ua.x;
            acc[2*q+1]   += c * ua.y;
            acc[8+2*q]   += c * uc.x;
            acc[8+2*q+1] += c * uc.y;
        }

        p0 = n0; p1 = n1;
    }

#pragma unroll
    for (int d = 0; d < 16; d++) ss[warp][d * 32 + j] = acc[d];
    __syncthreads();

    for (int idx = t; idx < JD_; idx += 256) {
        int d = idx >> 5, jj = idx & 31;
        float r = 0.f;
#pragma unroll
        for (int wi = 0; wi < 8; wi++) r += ss[wi][idx];
        g_part2[((size_t)ic * B_ + b) * JD_ + jj * 16 + d] = r;
    }
}

// ---------------------------------------------------------------------------
// Reduce g_part2 over 16 chunks, then squash.
// mode 0: g_v[0] = squash_J(s)             (v1)
// mode 1: g_v[1] = squash_J(s) + g_v[0]    (v1 + v2, additive logits)
// mode 2: out    = squash_D(s)
// ---------------------------------------------------------------------------
__global__ void k_squash(int mode, float* __restrict__ out) {
    const int b = blockIdx.x;
    const int t = threadIdx.x;     // t = j*16 + d
    const float* p = g_part2 + (size_t)b * JD_ + t;
    float s = 0.f;
#pragma unroll
    for (int ic = 0; ic < 16; ic++)
        s += p[(size_t)ic * B_ * JD_];

    if (mode == 2) {
        float q = s * s;
#pragma unroll
        for (int o = 1; o < 16; o <<= 1)   // 16 consecutive lanes = same j
            q += __shfl_xor_sync(0xffffffffu, q, o);
        out[b * JD_ + t] = s * (q / (1.f + q)) * rsqrtf(q + EPS_);
        return;
    }

    __shared__ float sq[16];
    if (t < 16) sq[t] = 0.f;
    __syncthreads();
    atomicAdd(&sq[t & 15], s * s);
    __syncthreads();
    float q = sq[t & 15];
    float v = s * (q / (1.f + q)) * rsqrtf(q + EPS_);
    if (mode == 0) g_v[0][b * JD_ + t] = v;
    else           g_v[1][b * JD_ + t] = v + g_v[0][b * JD_ + t];
}

// ---------------------------------------------------------------------------
extern "C" void kernel_launch(void* const* d_in, const int* in_sizes, int n_in,
                              void* d_out, int out_size) {
    const float* x = (const float*)d_in[0];
    const float* w = (const float*)d_in[1];
    if (in_sizes[0] != B_ * N_ * 16) {       // defensive input-order check
        x = (const float*)d_in[1];
        w = (const float*)d_in[0];
    }

    const int smemB = 16 * 16 * SROW * 2;    // 69632 B
    cudaFuncSetAttribute(k_u, cudaFuncAttributeMaxDynamicSharedMemorySize, smemB);

    k_u<<<NCH, 512, smemB>>>(x, w);              // u fp16 + s1 partials (148 chunks)
    k_red1<<<2048, 256>>>();                     // s1: 148 -> 16 chunks
    k_squash<<<B_, JD_>>>(0, nullptr);           // v1 = squash_J(s1)
    dim3 pg(16, B_);
    k_pass<<<pg, 256>>>(0);                      // iter 2: softmax(u.v1) -> s2
    k_squash<<<B_, JD_>>>(1, nullptr);           // vsum = squash_J(s2) + v1
    k_pass<<<pg, 256>>>(1);                      // final: softmax(u.vsum) -> s3
    k_squash<<<B_, JD_>>>(2, (float*)d_out);     // out = squash_D(s3)
}

// round 12
// speedup vs baseline: 1.1208x; 1.0022x over previous
#include <cuda_runtime.h>
#include <cuda_fp16.h>
#include <cstdint>

#define B_    64
#define N_    2048
#define JD_   512
#define EPS_  1e-8f
#define SROW  136   // smem row stride in halves (272 B): conflict-free frag stores
#define NCH   148   // k_u i-chunks: 124 CTAs x 14 i + 24 CTAs x 13 i = 2048
#define PCH   9     // k_pass i-chunks: 5 x 228 + 4 x 227 = 2048

// Scratch (device globals: allocation-free rule)
__device__ __half g_u[(size_t)B_ * N_ * JD_];        // 134 MB u[b][i][jd] fp16
__device__ float  g_part1[(size_t)NCH * B_ * JD_];   // s1 partials (148 chunks)
__device__ float  g_part2[(size_t)16 * B_ * JD_];    // reduced partials (<=16 chunks)
__device__ float  g_v[2][B_ * JD_];                  // v1, (v1+v2)

__device__ __forceinline__ uint32_t packh2(float a, float b) {
    __half2 h = __floats2half2_rn(a, b);
    return *(uint32_t*)&h;
}
__device__ __forceinline__ void mma16816(float& d0, float& d1, float& d2, float& d3,
        uint32_t a0, uint32_t a1, uint32_t a2, uint32_t a3,
        uint32_t b0, uint32_t b1) {
    asm volatile(
        "mma.sync.aligned.m16n8k16.row.col.f32.f16.f16.f32 "
        "{%0,%1,%2,%3}, {%4,%5,%6,%7}, {%8,%9}, {%10,%11,%12,%13};\n"
        : "=f"(d0), "=f"(d1), "=f"(d2), "=f"(d3)
        : "r"(a0), "r"(a1), "r"(a2), "r"(a3), "r"(b0), "r"(b1),
          "f"(0.f), "f"(0.f), "f"(0.f), "f"(0.f));
}

// ---------------------------------------------------------------------------
// k_u (round-11 proven): tensor-core einsum -> u (fp16, coalesced via smem
// transpose) + fused pass-1 partials (uniform c = 1/32, fp32 acc).
// Grid 148 (one CTA per SM; 14 or 13 i each), 512 thr = 16 warps;
// warp = (mt: 16 b) x (jdr: 128 jd).
// ---------------------------------------------------------------------------
__global__ __launch_bounds__(512, 1) void k_u(const float* __restrict__ x,
                                              const float* __restrict__ w) {
    extern __shared__ __half us[];       // 16 warps * 16 rows * SROW halves
    const int cta  = blockIdx.x;
    const int nI   = (cta < 124) ? 14 : 13;
    const int ib   = (cta < 124) ? cta * 14 : 1736 + (cta - 124) * 13;
    const int t    = threadIdx.x;
    const int wid  = t >> 5;
    const int lane = t & 31;
    const int g    = lane >> 2;
    const int tg   = lane & 3;
    const int mt   = wid & 3;
    const int jdr  = wid >> 2;
    const int jd0  = jdr * 128;
    const int row0 = mt * 16 + g;
    const int row1 = row0 + 8;
    __half* usw = us + wid * 16 * SROW;  // this warp's 16x128 tile

    float acc[16][4];
#pragma unroll
    for (int q = 0; q < 16; q++)
#pragma unroll
        for (int r = 0; r < 4; r++) acc[q][r] = 0.f;

    for (int k = 0; k < nI; k++) {
        const int i = ib + k;

        // A fragment from fp32 x
        const float* xp0 = x + ((size_t)row0 * N_ + i) * 16 + 2 * tg;
        const float* xp1 = x + ((size_t)row1 * N_ + i) * 16 + 2 * tg;
        float2 f0 = *(const float2*)xp0;
        float2 f1 = *(const float2*)xp1;
        float2 f2 = *(const float2*)(xp0 + 8);
        float2 f3 = *(const float2*)(xp1 + 8);
        uint32_t A0 = packh2(f0.x, f0.y);
        uint32_t A1 = packh2(f1.x, f1.y);
        uint32_t A2 = packh2(f2.x, f2.y);
        uint32_t A3 = packh2(f3.x, f3.y);

#pragma unroll
        for (int q = 0; q < 16; q++) {
            const int col = jd0 + q * 8 + g;
            const float* wp = w + ((size_t)i * JD_ + col) * 16 + 2 * tg;
            float2 w0 = *(const float2*)wp;
            float2 w1 = *(const float2*)(wp + 8);
            uint32_t Bb0 = packh2(w0.x, w0.y);
            uint32_t Bb1 = packh2(w1.x, w1.y);

            float d0, d1, d2, d3;
            mma16816(d0, d1, d2, d3, A0, A1, A2, A3, Bb0, Bb1);
            acc[q][0] += d0; acc[q][1] += d1;
            acc[q][2] += d2; acc[q][3] += d3;

            // stage fragments: row-local col q*8+2tg, rows g / g+8
            *(uint32_t*)(usw + g * SROW       + q * 8 + 2 * tg) = packh2(d0, d1);
            *(uint32_t*)(usw + (g + 8) * SROW + q * 8 + 2 * tg) = packh2(d2, d3);
        }
        __syncwarp();

        // coalesced copy-out: 16 rows x 256 B -> u[b][i][jd0..jd0+128) (streamed)
#pragma unroll
        for (int it = 0; it < 8; it++) {
            const int r   = it * 2 + (lane >> 4);
            const int off = lane & 15;
            uint4 v = *(const uint4*)(usw + r * SROW + off * 8);
            __stcs((uint4*)(g_u + ((size_t)(mt * 16 + r) * N_ + i) * JD_
                            + jd0 + off * 8), v);
        }
        __syncwarp();
    }

    // s1 partials: g_part1[cta][b][jd], scaled by 1/32
    float* pb = g_part1 + ((size_t)cta * B_ + row0) * JD_;
    const float cinv = 1.0f / 32.0f;
#pragma unroll
    for (int q = 0; q < 16; q++) {
        const int col = jd0 + q * 8 + 2 * tg;
        *(float2*)(pb + col)           = make_float2(acc[q][0] * cinv, acc[q][1] * cinv);
        *(float2*)(pb + 8 * JD_ + col) = make_float2(acc[q][2] * cinv, acc[q][3] * cinv);
    }
}

// ---------------------------------------------------------------------------
// Stage A of s1 reduce: 148 chunks -> 16 groups (12 groups of 9 + 4 of 10).
// ---------------------------------------------------------------------------
__global__ void k_red1() {
    const int gidx = blockIdx.x * 256 + threadIdx.x;
    const int grp  = gidx >> 15;                       // 0..15 (B_*JD_ = 32768)
    const int idx  = gidx & 32767;
    const int cnt  = (grp < 12) ? 9 : 10;
    const int base = (grp < 12) ? grp * 9 : 108 + (grp - 12) * 10;
    const float* p = g_part1 + (size_t)base * (B_ * JD_) + idx;
    float s = 0.f;
#pragma unroll 10
    for (int c = 0; c < cnt; c++)
        s += p[(size_t)c * B_ * JD_];
    g_part2[(size_t)grp * (B_ * JD_) + idx] = s;
}

// ---------------------------------------------------------------------------
// Routing sweep over fp16 u, depth-1 prefetch, no max-subtraction softmax
// (round-9 proven inner loop). Grid (9, 64) = 576 CTAs = ONE full wave at
// 4 CTAs/SM (was 1024 CTAs = 1.73 waves). Warp covers 28-29 i of one b.
// ---------------------------------------------------------------------------
__global__ __launch_bounds__(256, 4) void k_pass(int vIdx) {
    const int b    = blockIdx.y;
    const int c    = blockIdx.x;           // 0..8
    const int t    = threadIdx.x;
    const int warp = t >> 5;
    const int j    = t & 31;

    __shared__ float vs[JD_];
    __shared__ float ss[8][JD_];

    for (int idx = t; idx < JD_; idx += 256)
        vs[idx] = g_v[vIdx][b * JD_ + idx];
    __syncthreads();

    __half2 vj2[8];
#pragma unroll
    for (int q = 0; q < 8; q++)
        vj2[q] = __floats2half2_rn(vs[j * 16 + 2 * q], vs[j * 16 + 2 * q + 1]);

    float acc[16];
#pragma unroll
    for (int d = 0; d < 16; d++) acc[d] = 0.f;

    // chunk c: [base, base+len); warp sub-range of n = 28 or 29 i's
    const int base = (c < 5) ? c * 228 : 1140 + (c - 5) * 227;
    const int len  = (c < 5) ? 228 : 227;
    const int qn   = len >> 3, rem = len & 7;
    const int n    = qn + (warp < rem ? 1 : 0);
    const int i0   = base + warp * qn + ((warp < rem) ? warp : rem);

    const uint4* ub = (const uint4*)(g_u + ((size_t)b * N_ + i0) * JD_) + j * 2;

    uint4 p0 = __ldcs(ub);
    uint4 p1 = __ldcs(ub + 1);
    for (int k = 0; k < n; k++) {
        // prefetch next i (clamped; MLP overlap with softmax latency)
        const int kn = (k < n - 1) ? k + 1 : n - 1;
        uint4 n0 = __ldcs(ub + (size_t)kn * 64);
        uint4 n1 = __ldcs(ub + (size_t)kn * 64 + 1);

        // logit in half2
        const __half2* u2a = (const __half2*)&p0;
        const __half2* u2b = (const __half2*)&p1;
        __half2 h = __hmul2(u2a[0], vj2[0]);
#pragma unroll
        for (int q = 1; q < 4; q++) h = __hfma2(u2a[q], vj2[q], h);
#pragma unroll
        for (int q = 0; q < 4; q++) h = __hfma2(u2b[q], vj2[4 + q], h);
        float bl = __low2float(h) + __high2float(h);

        // softmax over 32 j-lanes, no max-subtraction (bounded logits)
        float ex = __expf(bl);
        float sum = ex;
#pragma unroll
        for (int o = 16; o > 0; o >>= 1)
            sum += __shfl_xor_sync(0xffffffffu, sum, o);
        const float cc = __fdividef(ex, sum);

        // acc += c * u (fp32 unpack)
#pragma unroll
        for (int q = 0; q < 4; q++) {
            float2 ua = __half22float2(u2a[q]);
            float2 uc = __half22float2(u2b[q]);
            acc[2*q]     += cc * ua.x;
            acc[2*q+1]   += cc * ua.y;
            acc[8+2*q]   += cc * uc.x;
            acc[8+2*q+1] += cc * uc.y;
        }

        p0 = n0; p1 = n1;
    }

#pragma unroll
    for (int d = 0; d < 16; d++) ss[warp][d * 32 + j] = acc[d];
    __syncthreads();

    for (int idx = t; idx < JD_; idx += 256) {
        int d = idx >> 5, jj = idx & 31;
        float r = 0.f;
#pragma unroll
        for (int wi = 0; wi < 8; wi++) r += ss[wi][idx];
        g_part2[((size_t)c * B_ + b) * JD_ + jj * 16 + d] = r;
    }
}

// ---------------------------------------------------------------------------
// Reduce g_part2 over cnt chunks, then squash.
// mode 0: g_v[0] = squash_J(s)             (v1)
// mode 1: g_v[1] = squash_J(s) + g_v[0]    (v1 + v2, additive logits)
// mode 2: out    = squash_D(s)
// ---------------------------------------------------------------------------
__global__ void k_squash(int mode, int cnt, float* __restrict__ out) {
    const int b = blockIdx.x;
    const int t = threadIdx.x;     // t = j*16 + d
    const float* p = g_part2 + (size_t)b * JD_ + t;
    float s = 0.f;
#pragma unroll 16
    for (int ic = 0; ic < cnt; ic++)
        s += p[(size_t)ic * B_ * JD_];

    if (mode == 2) {
        float q = s * s;
#pragma unroll
        for (int o = 1; o < 16; o <<= 1)   // 16 consecutive lanes = same j
            q += __shfl_xor_sync(0xffffffffu, q, o);
        out[b * JD_ + t] = s * (q / (1.f + q)) * rsqrtf(q + EPS_);
        return;
    }

    __shared__ float sq[16];
    if (t < 16) sq[t] = 0.f;
    __syncthreads();
    atomicAdd(&sq[t & 15], s * s);
    __syncthreads();
    float q = sq[t & 15];
    float v = s * (q / (1.f + q)) * rsqrtf(q + EPS_);
    if (mode == 0) g_v[0][b * JD_ + t] = v;
    else           g_v[1][b * JD_ + t] = v + g_v[0][b * JD_ + t];
}

// ---------------------------------------------------------------------------
extern "C" void kernel_launch(void* const* d_in, const int* in_sizes, int n_in,
                              void* d_out, int out_size) {
    const float* x = (const float*)d_in[0];
    const float* w = (const float*)d_in[1];
    if (in_sizes[0] != B_ * N_ * 16) {       // defensive input-order check
        x = (const float*)d_in[1];
        w = (const float*)d_in[0];
    }

    const int smemB = 16 * 16 * SROW * 2;    // 69632 B
    cudaFuncSetAttribute(k_u, cudaFuncAttributeMaxDynamicSharedMemorySize, smemB);

    k_u<<<NCH, 512, smemB>>>(x, w);              // u fp16 + s1 partials (148 chunks)
    k_red1<<<2048, 256>>>();                     // s1: 148 -> 16 chunks
    k_squash<<<B_, JD_>>>(0, 16, nullptr);       // v1 = squash_J(s1)
    dim3 pg(PCH, B_);
    k_pass<<<pg, 256>>>(0);                      // iter 2: softmax(u.v1) -> s2
    k_squash<<<B_, JD_>>>(1, PCH, nullptr);      // vsum = squash_J(s2) + v1
    k_pass<<<pg, 256>>>(1);                      // final: softmax(u.vsum) -> s3
    k_squash<<<B_, JD_>>>(2, PCH, (float*)d_out);// out = squash_D(s3)
}

// round 13
// speedup vs baseline: 1.1892x; 1.0610x over previous
#include <cuda_runtime.h>
#include <cuda_fp16.h>
#include <cstdint>

#define B_    64
#define N_    2048
#define JD_   512
#define BJD   (B_ * JD_)
#define EPS_  1e-8f
#define SROW  136   // smem row stride in halves (272 B): conflict-free frag stores
#define NCH   148   // k_u i-chunks: 124 CTAs x 14 i + 24 CTAs x 13 i = 2048
#define PCH   9     // k_pass i-chunks: 5 x 228 + 4 x 227 = 2048

// Scratch (device globals: allocation-free rule)
__device__ __half g_u[(size_t)B_ * N_ * JD_];     // 134 MB u[b][i][jd] fp16
__device__ float  g_part1[(size_t)NCH * BJD];     // s1 partials (148 chunks)
__device__ float  g_s1r[(size_t)16 * BJD];        // s1 reduced to 16 chunks
__device__ float  g_p3[(size_t)PCH * BJD];        // s2 partials (9 chunks)
__device__ float  g_p4[(size_t)PCH * BJD];        // s3 partials (9 chunks)

__device__ __forceinline__ uint32_t packh2(float a, float b) {
    __half2 h = __floats2half2_rn(a, b);
    return *(uint32_t*)&h;
}
__device__ __forceinline__ void mma16816(float& d0, float& d1, float& d2, float& d3,
        uint32_t a0, uint32_t a1, uint32_t a2, uint32_t a3,
        uint32_t b0, uint32_t b1) {
    asm volatile(
        "mma.sync.aligned.m16n8k16.row.col.f32.f16.f16.f32 "
        "{%0,%1,%2,%3}, {%4,%5,%6,%7}, {%8,%9}, {%10,%11,%12,%13};\n"
        : "=f"(d0), "=f"(d1), "=f"(d2), "=f"(d3)
        : "r"(a0), "r"(a1), "r"(a2), "r"(a3), "r"(b0), "r"(b1),
          "f"(0.f), "f"(0.f), "f"(0.f), "f"(0.f));
}

// ---------------------------------------------------------------------------
// k_u (round-11 proven): tensor-core einsum -> u (fp16, coalesced via smem
// transpose) + fused pass-1 partials (uniform c = 1/32, fp32 acc).
// Grid 148 (one CTA per SM; 14 or 13 i each), 512 thr = 16 warps;
// warp = (mt: 16 b) x (jdr: 128 jd).
// ---------------------------------------------------------------------------
__global__ __launch_bounds__(512, 1) void k_u(const float* __restrict__ x,
                                              const float* __restrict__ w) {
    extern __shared__ __half us[];       // 16 warps * 16 rows * SROW halves
    const int cta  = blockIdx.x;
    const int nI   = (cta < 124) ? 14 : 13;
    const int ib   = (cta < 124) ? cta * 14 : 1736 + (cta - 124) * 13;
    const int t    = threadIdx.x;
    const int wid  = t >> 5;
    const int lane = t & 31;
    const int g    = lane >> 2;
    const int tg   = lane & 3;
    const int mt   = wid & 3;
    const int jdr  = wid >> 2;
    const int jd0  = jdr * 128;
    const int row0 = mt * 16 + g;
    const int row1 = row0 + 8;
    __half* usw = us + wid * 16 * SROW;  // this warp's 16x128 tile

    float acc[16][4];
#pragma unroll
    for (int q = 0; q < 16; q++)
#pragma unroll
        for (int r = 0; r < 4; r++) acc[q][r] = 0.f;

    for (int k = 0; k < nI; k++) {
        const int i = ib + k;

        // A fragment from fp32 x
        const float* xp0 = x + ((size_t)row0 * N_ + i) * 16 + 2 * tg;
        const float* xp1 = x + ((size_t)row1 * N_ + i) * 16 + 2 * tg;
        float2 f0 = *(const float2*)xp0;
        float2 f1 = *(const float2*)xp1;
        float2 f2 = *(const float2*)(xp0 + 8);
        float2 f3 = *(const float2*)(xp1 + 8);
        uint32_t A0 = packh2(f0.x, f0.y);
        uint32_t A1 = packh2(f1.x, f1.y);
        uint32_t A2 = packh2(f2.x, f2.y);
        uint32_t A3 = packh2(f3.x, f3.y);

#pragma unroll
        for (int q = 0; q < 16; q++) {
            const int col = jd0 + q * 8 + g;
            const float* wp = w + ((size_t)i * JD_ + col) * 16 + 2 * tg;
            float2 w0 = *(const float2*)wp;
            float2 w1 = *(const float2*)(wp + 8);
            uint32_t Bb0 = packh2(w0.x, w0.y);
            uint32_t Bb1 = packh2(w1.x, w1.y);

            float d0, d1, d2, d3;
            mma16816(d0, d1, d2, d3, A0, A1, A2, A3, Bb0, Bb1);
            acc[q][0] += d0; acc[q][1] += d1;
            acc[q][2] += d2; acc[q][3] += d3;

            // stage fragments: row-local col q*8+2tg, rows g / g+8
            *(uint32_t*)(usw + g * SROW       + q * 8 + 2 * tg) = packh2(d0, d1);
            *(uint32_t*)(usw + (g + 8) * SROW + q * 8 + 2 * tg) = packh2(d2, d3);
        }
        __syncwarp();

        // coalesced copy-out: 16 rows x 256 B -> u[b][i][jd0..jd0+128) (streamed)
#pragma unroll
        for (int it = 0; it < 8; it++) {
            const int r   = it * 2 + (lane >> 4);
            const int off = lane & 15;
            uint4 v = *(const uint4*)(usw + r * SROW + off * 8);
            __stcs((uint4*)(g_u + ((size_t)(mt * 16 + r) * N_ + i) * JD_
                            + jd0 + off * 8), v);
        }
        __syncwarp();
    }

    // s1 partials: g_part1[cta][b][jd], scaled by 1/32
    float* pb = g_part1 + ((size_t)cta * B_ + row0) * JD_;
    const float cinv = 1.0f / 32.0f;
#pragma unroll
    for (int q = 0; q < 16; q++) {
        const int col = jd0 + q * 8 + 2 * tg;
        *(float2*)(pb + col)           = make_float2(acc[q][0] * cinv, acc[q][1] * cinv);
        *(float2*)(pb + 8 * JD_ + col) = make_float2(acc[q][2] * cinv, acc[q][3] * cinv);
    }
}

// ---------------------------------------------------------------------------
// Stage A of s1 reduce: 148 chunks -> 16 groups (12 groups of 9 + 4 of 10).
// ---------------------------------------------------------------------------
__global__ void k_red1() {
    const int gidx = blockIdx.x * 256 + threadIdx.x;
    const int grp  = gidx >> 15;                       // 0..15 (BJD = 32768)
    const int idx  = gidx & 32767;
    const int cnt  = (grp < 12) ? 9 : 10;
    const int base = (grp < 12) ? grp * 9 : 108 + (grp - 12) * 10;
    const float* p = g_part1 + (size_t)base * BJD + idx;
    float s = 0.f;
#pragma unroll 10
    for (int c = 0; c < cnt; c++)
        s += p[(size_t)c * BJD];
    g_s1r[(size_t)grp * BJD + idx] = s;
}

// ---------------------------------------------------------------------------
// Routing sweep with FUSED v-prologue: each CTA recomputes v for its b from
// the partial chunks (L2-resident; 2us) instead of a separate squash kernel.
//   mode 0: v = squash_J(s1)              [s1 from g_s1r, 16 chunks] -> g_p3
//   mode 1: v = squash_J(s1)+squash_J(s2) [s2 from g_p3, 9 chunks]   -> g_p4
// Main loop: round-12 proven (depth-1 prefetch, no-max softmax, 1 full wave).
// Grid (9, 64), 256 thr = 8 warps; warp covers 28-29 i of one b, lane = j.
// ---------------------------------------------------------------------------
__global__ __launch_bounds__(256, 4) void k_pass(int mode) {
    const int b    = blockIdx.y;
    const int c    = blockIdx.x;           // 0..8
    const int t    = threadIdx.x;
    const int warp = t >> 5;
    const int j    = t & 31;

    __shared__ float vs[JD_];
    __shared__ float ss[8][JD_];
    __shared__ float sqA[16];
    __shared__ float sqB[16];

    // ---- fused v prologue: elements t (j = t>>4) and t+256 (j = 16 + t>>4)
    {
        if (t < 16) { sqA[t] = 0.f; sqB[t] = 0.f; }
        float s1a = 0.f, s1b = 0.f;
        const float* p1 = g_s1r + b * JD_ + t;
#pragma unroll
        for (int ic = 0; ic < 16; ic++) {
            s1a += p1[(size_t)ic * BJD];
            s1b += p1[(size_t)ic * BJD + 256];
        }
        float s2a = 0.f, s2b = 0.f;
        if (mode) {
            const float* p2 = g_p3 + b * JD_ + t;
#pragma unroll
            for (int ic = 0; ic < PCH; ic++) {
                s2a += p2[(size_t)ic * BJD];
                s2b += p2[(size_t)ic * BJD + 256];
            }
        }
        __syncthreads();
        atomicAdd(&sqA[t & 15], s1a * s1a + s1b * s1b);
        if (mode) atomicAdd(&sqB[t & 15], s2a * s2a + s2b * s2b);
        __syncthreads();
        const float qa = sqA[t & 15];
        const float fa = (qa / (1.f + qa)) * rsqrtf(qa + EPS_);
        float va = s1a * fa, vb = s1b * fa;
        if (mode) {
            const float qb = sqB[t & 15];
            const float fb = (qb / (1.f + qb)) * rsqrtf(qb + EPS_);
            va += s2a * fb; vb += s2b * fb;
        }
        vs[t] = va; vs[t + 256] = vb;
        __syncthreads();
    }

    __half2 vj2[8];
#pragma unroll
    for (int q = 0; q < 8; q++)
        vj2[q] = __floats2half2_rn(vs[j * 16 + 2 * q], vs[j * 16 + 2 * q + 1]);

    float acc[16];
#pragma unroll
    for (int d = 0; d < 16; d++) acc[d] = 0.f;

    // chunk c: [base, base+len); warp sub-range of n = 28 or 29 i's
    const int base = (c < 5) ? c * 228 : 1140 + (c - 5) * 227;
    const int len  = (c < 5) ? 228 : 227;
    const int qn   = len >> 3, rem = len & 7;
    const int n    = qn + (warp < rem ? 1 : 0);
    const int i0   = base + warp * qn + ((warp < rem) ? warp : rem);

    const uint4* ub = (const uint4*)(g_u + ((size_t)b * N_ + i0) * JD_) + j * 2;

    uint4 p0 = __ldcs(ub);
    uint4 p1 = __ldcs(ub + 1);
    for (int k = 0; k < n; k++) {
        // prefetch next i (clamped; MLP overlap with softmax latency)
        const int kn = (k < n - 1) ? k + 1 : n - 1;
        uint4 n0 = __ldcs(ub + (size_t)kn * 64);
        uint4 n1 = __ldcs(ub + (size_t)kn * 64 + 1);

        // logit in half2
        const __half2* u2a = (const __half2*)&p0;
        const __half2* u2b = (const __half2*)&p1;
        __half2 h = __hmul2(u2a[0], vj2[0]);
#pragma unroll
        for (int q = 1; q < 4; q++) h = __hfma2(u2a[q], vj2[q], h);
#pragma unroll
        for (int q = 0; q < 4; q++) h = __hfma2(u2b[q], vj2[4 + q], h);
        float bl = __low2float(h) + __high2float(h);

        // softmax over 32 j-lanes, no max-subtraction (bounded logits)
        float ex = __expf(bl);
        float sum = ex;
#pragma unroll
        for (int o = 16; o > 0; o >>= 1)
            sum += __shfl_xor_sync(0xffffffffu, sum, o);
        const float cc = __fdividef(ex, sum);

        // acc += c * u (fp32 unpack)
#pragma unroll
        for (int q = 0; q < 4; q++) {
            float2 ua = __half22float2(u2a[q]);
            float2 uc = __half22float2(u2b[q]);
            acc[2*q]     += cc * ua.x;
            acc[2*q+1]   += cc * ua.y;
            acc[8+2*q]   += cc * uc.x;
            acc[8+2*q+1] += cc * uc.y;
        }

        p0 = n0; p1 = n1;
    }

#pragma unroll
    for (int d = 0; d < 16; d++) ss[warp][d * 32 + j] = acc[d];
    __syncthreads();

    float* dst = mode ? g_p4 : g_p3;
    for (int idx = t; idx < JD_; idx += 256) {
        int d = idx >> 5, jj = idx & 31;
        float r = 0.f;
#pragma unroll
        for (int wi = 0; wi < 8; wi++) r += ss[wi][idx];
        dst[((size_t)c * B_ + b) * JD_ + jj * 16 + d] = r;
    }
}

// ---------------------------------------------------------------------------
// Final: reduce s3 partials (9 chunks) + squash over D -> output.
// ---------------------------------------------------------------------------
__global__ void k_final(float* __restrict__ out) {
    const int b = blockIdx.x;
    const int t = threadIdx.x;     // t = j*16 + d
    const float* p = g_p4 + (size_t)b * JD_ + t;
    float s = 0.f;
#pragma unroll
    for (int ic = 0; ic < PCH; ic++)
        s += p[(size_t)ic * BJD];

    float q = s * s;
#pragma unroll
    for (int o = 1; o < 16; o <<= 1)   // 16 consecutive lanes = same j
        q += __shfl_xor_sync(0xffffffffu, q, o);
    out[b * JD_ + t] = s * (q / (1.f + q)) * rsqrtf(q + EPS_);
}

// ---------------------------------------------------------------------------
extern "C" void kernel_launch(void* const* d_in, const int* in_sizes, int n_in,
                              void* d_out, int out_size) {
    const float* x = (const float*)d_in[0];
    const float* w = (const float*)d_in[1];
    if (in_sizes[0] != B_ * N_ * 16) {       // defensive input-order check
        x = (const float*)d_in[1];
        w = (const float*)d_in[0];
    }

    const int smemB = 16 * 16 * SROW * 2;    // 69632 B
    cudaFuncSetAttribute(k_u, cudaFuncAttributeMaxDynamicSharedMemorySize, smemB);

    k_u<<<NCH, 512, smemB>>>(x, w);          // u fp16 + s1 partials (148 chunks)
    k_red1<<<2048, 256>>>();                 // s1: 148 -> 16 chunks
    dim3 pg(PCH, B_);
    k_pass<<<pg, 256>>>(0);                  // v1 in-prologue; softmax(u.v1) -> s2
    k_pass<<<pg, 256>>>(1);                  // vsum in-prologue; softmax -> s3
    k_final<<<B_, JD_>>>((float*)d_out);     // out = squash_D(s3)
}